// round 15
// baseline (speedup 1.0000x reference)
#include <cuda_runtime.h>
#include <math.h>

#define IMGS  16
#define H     256
#define W     256
#define NPIX  (H * W)            // 65536
#define TOTAL (IMGS * NPIX)      // 1048576
#define BIG2  1.0e12f            // "no opposite pixel within vertical window"
#define GUARD 9.0f               // exactness guard: excluded cands >= 9
#define NSLAB 32                 // 8-column slabs per image
#define NBLK  (IMGS * NSLAB)     // 512 blocks, fully independent

// ---- accumulators (static __device__; allocation-free per harness rules) ----
__device__ float  d_maxabs[IMGS];
__device__ int    d_counts[IMGS];
__device__ double d_S[IMGS];
__device__ unsigned int d_done;

__device__ __forceinline__ float sqrt_approx(float x) {
    float r;
    asm("sqrt.approx.f32 %0, %1;" : "=f"(r) : "f"(x));
    return r;
}
__device__ __forceinline__ float tanh_approx(float x) {
    float r;
    asm("tanh.approx.f32 %0, %1;" : "=f"(r) : "f"(x));
    return r;
}

// ---------------------------------------------------------------------------
// Single fused kernel, Phase-B-free.
// Block = one 8-column slab (+2 halo cols -> 12 cols, self-contained for the
// +-2 min-plus window). Phase A: thread r builds a 12-bit row mask from an
// aligned 16-float target window; warp ballots transpose into per-column
// 256-row bitmasks (cmask). ONE sync. Then each thread computes, fully in
// registers, the +-8-row windowed vertical distance per column (funnel-shift
// + clz/ffs on cmask) -> signed v^2, the +-2-col min-plus (guard 9: excluded
// candidates have |dx|>=3 (>=9) or |dy|>=9 (>=81), so bm<=9 is exact), the
// sigmoid, and the block reduction. Rare fallback scans all rows x 12 cols of
// cmask. Last block finalizes + resets replay state.
__global__ void __launch_bounds__(256, 4)
fused_kernel(const float* __restrict__ pred, const float* __restrict__ target,
             float* __restrict__ out) {
    __shared__ unsigned cmask[12][8];   // per-column 32-row segment bitmasks
    __shared__ float    wred[16];       // 8 warp maxes + 8 warp sums
    __shared__ int      cred[8];        // 8 warp fg-counts
    __shared__ int      is_last;

    int blk  = blockIdx.x;
    int tid  = threadIdx.x;
    int b    = blk >> 5;                // image
    int slab = blk & 31;
    int x0   = slab * 8;
    int r    = tid;                     // this thread's row
    int base = b * NPIX + r * W;
    int warp = tid >> 5, lane = tid & 31;

    // ---- Phase A: masks + pred (front-batched loads) ----
    int wbase = min(max(x0 - 4, 0), W - 16);            // 4-aligned 16-float window
    const float4* tp = (const float4*)(target + base + wbase);
    float4 t0 = tp[0], t1 = tp[1], t2 = tp[2], t3 = tp[3];
    float4 pA = *(const float4*)(pred + base + x0);
    float4 pB = *(const float4*)(pred + base + x0 + 4);

    unsigned mw = 0;
    mw |= (t0.x > 0.5f) ? 1u << 0  : 0u;  mw |= (t0.y > 0.5f) ? 1u << 1  : 0u;
    mw |= (t0.z > 0.5f) ? 1u << 2  : 0u;  mw |= (t0.w > 0.5f) ? 1u << 3  : 0u;
    mw |= (t1.x > 0.5f) ? 1u << 4  : 0u;  mw |= (t1.y > 0.5f) ? 1u << 5  : 0u;
    mw |= (t1.z > 0.5f) ? 1u << 6  : 0u;  mw |= (t1.w > 0.5f) ? 1u << 7  : 0u;
    mw |= (t2.x > 0.5f) ? 1u << 8  : 0u;  mw |= (t2.y > 0.5f) ? 1u << 9  : 0u;
    mw |= (t2.z > 0.5f) ? 1u << 10 : 0u;  mw |= (t2.w > 0.5f) ? 1u << 11 : 0u;
    mw |= (t3.x > 0.5f) ? 1u << 12 : 0u;  mw |= (t3.y > 0.5f) ? 1u << 13 : 0u;
    mw |= (t3.z > 0.5f) ? 1u << 14 : 0u;  mw |= (t3.w > 0.5f) ? 1u << 15 : 0u;

    // rowmask bit j <-> global col clamp(x0-2+j, 0, 255); image-edge halo
    // duplicates the edge column (dominated under max(sg*s+k^2, k^2) -> exact)
    unsigned rm;
    if (slab == 0)            rm = ((mw & 1u) * 3u) | ((mw & 0x3FFu) << 2);
    else if (slab == NSLAB-1) rm = ((mw >> 6) & 0x3FFu) | (((mw >> 15) & 1u) ? (3u << 10) : 0u);
    else                      rm = (mw >> 2) & 0xFFFu;

    int cnt = __popc(rm & 0x3FCu);      // own cols only (j = 2..9)

    #pragma unroll
    for (int j = 0; j < 12; j++) {
        unsigned bal = __ballot_sync(0xffffffffu, (rm >> j) & 1u);
        if (lane == j) cmask[j][warp] = bal;
    }
    __syncthreads();                    // the ONLY pre-reduction barrier

    // ---- vertical window distances, per-thread, in registers ----
    // win bit i <-> row r-8+i (17 bits). validm zeroes out-of-image rows.
    int wlo   = (r - 8) >> 5;           // arithmetic shift: -1 for r < 8
    int shift = (r - 8) & 31;
    unsigned validm = 0x1FFFFu;
    if (r < 8)   validm &= ~((1u << (8 - r)) - 1u);
    if (r > 247) validm &= (1u << (264 - r)) - 1u;

    float v[12];
    #pragma unroll
    for (int j = 0; j < 12; j++) {
        unsigned lo = (wlo >= 0) ? cmask[j][wlo] : 0u;
        unsigned hi = (wlo <  7) ? cmask[j][wlo + 1] : 0u;
        unsigned long long comb = ((unsigned long long)hi << 32) | (unsigned long long)lo;
        unsigned win = (unsigned)(comb >> shift) & 0x1FFFFu;
        unsigned fgb = (win >> 8) & 1u;
        unsigned opp = (fgb ? ~win : win) & validm;
        unsigned up  = opp & 0xFFu;          // bit i <-> dist 8-i above
        unsigned dn  = opp >> 9;             // bit i <-> dist i+1 below
        int du = up ? (__clz(up) - 23) : 100;
        int dd = dn ? __ffs(dn)        : 100;
        int d  = min(du, dd);
        float v2 = (d > 8) ? BIG2 : (float)(d * d);
        v[j] = fgb ? v2 : -v2;
    }

    // ---- horizontal min-plus window (candidate = max(sg*s[q]+k^2, k^2)) ----
    float bm[8];
    #pragma unroll
    for (int p = 0; p < 8; p++) {            // own col = local j = p+2
        float so = v[p + 2];
        float g  = (so > 0.f) ? 1.f : -1.f;
        float m0 = fmaxf(g * so, 0.f);
        float m1 = fmaxf(fmaf(g, v[p + 1], 1.f), 1.f);
        float m2 = fmaxf(fmaf(g, v[p + 3], 1.f), 1.f);
        float m3 = fmaxf(fmaf(g, v[p],     4.f), 4.f);
        float m4 = fmaxf(fmaf(g, v[p + 4], 4.f), 4.f);
        bm[p] = fminf(fminf(m0, fminf(m1, m2)), fminf(m3, m4));
    }

    // deferred exact-in-slab fallback: all 256 rows x 12 cols from cmask
    bool need = false;
    #pragma unroll
    for (int p = 0; p < 8; p++) need |= (bm[p] > GUARD);
    if (__any_sync(0xffffffffu, need)) {
        #pragma unroll
        for (int p = 0; p < 8; p++) {
            if (bm[p] > GUARD) {
                bool fg = (v[p + 2] > 0.f);
                float m = bm[p];
                for (int j = 0; j < 12; j++) {
                    float dx2 = (float)((p + 2 - j) * (p + 2 - j));
                    #pragma unroll 1
                    for (int y = 0; y < H; y++) {
                        bool bit = (cmask[j][y >> 5] >> (y & 31)) & 1u;
                        if (bit != fg) {
                            float dy = (float)(r - y);
                            m = fminf(m, fmaf(dy, dy, dx2));
                        }
                    }
                }
                bm[p] = m;
            }
        }
    }

    // ---- sigmoid, signed distance, dual accumulator chains ----
    float pv[8] = {pA.x, pA.y, pA.z, pA.w, pB.x, pB.y, pB.z, pB.w};
    float tA = 0.f, tB = 0.f, aA = 0.f, aB = 0.f;
    #pragma unroll
    for (int p = 0; p < 8; p++) {
        float sd   = sqrt_approx(bm[p]);           // bm >= 1 always
        float prob = fmaf(0.5f, tanh_approx(0.5f * pv[p]), 0.5f);
        float sds  = (v[p + 2] > 0.f) ? -sd : sd;  // signed distance
        if (p & 1) { aB = fmaxf(aB, sd); tB = fmaf(prob, sds, tB); }
        else       { aA = fmaxf(aA, sd); tA = fmaf(prob, sds, tA); }
    }
    float term = tA + tB;
    float amax = fmaxf(aA, aB);

    #pragma unroll
    for (int o = 16; o; o >>= 1) {
        amax = fmaxf(amax, __shfl_xor_sync(0xffffffffu, amax, o));
        term +=            __shfl_xor_sync(0xffffffffu, term, o);
        cnt  +=            __shfl_xor_sync(0xffffffffu, cnt,  o);
    }
    if (lane == 0) { wred[warp] = amax; wred[8 + warp] = term; cred[warp] = cnt; }
    __syncthreads();

    if (tid == 0) {
        float  mx = wred[0];
        double sm = (double)wred[8];
        int    cc = cred[0];
        #pragma unroll
        for (int i = 1; i < 8; i++) {
            mx = fmaxf(mx, wred[i]); sm += (double)wred[8 + i]; cc += cred[i];
        }
        atomicMax((int*)&d_maxabs[b], __float_as_int(mx));   // non-neg floats order as ints
        atomicAdd(&d_S[b], sm);
        atomicAdd(&d_counts[b], cc);
        __threadfence();
        unsigned int old = atomicAdd(&d_done, 1u);
        is_last = (old == (unsigned)(NBLK - 1)) ? 1 : 0;
    }
    __syncthreads();

    if (is_last) {
        __threadfence();
        double contrib = 0.0;
        if (tid < IMGS) {
            int    cc = __ldcg(&d_counts[tid]);
            float  mx = __ldcg(&d_maxabs[tid]);
            double S  = __ldcg(&d_S[tid]);
            if (cc > 0 && cc < NPIX)
                contrib = S / ((double)mx + 1e-6);
        }
        if (tid < 32) {
            #pragma unroll
            for (int o = 16; o; o >>= 1)
                contrib += __shfl_xor_sync(0xffffffffu, contrib, o);
            if (tid == 0) *out = (float)(contrib / (double)TOTAL);
        }
        // reset accumulators for the next graph replay
        if (tid < IMGS) { d_S[tid] = 0.0; d_maxabs[tid] = 0.0f; d_counts[tid] = 0; }
        if (tid == 0)   d_done = 0u;
    }
}

// ---------------------------------------------------------------------------
extern "C" void kernel_launch(void* const* d_in, const int* in_sizes, int n_in,
                              void* d_out, int out_size) {
    const float* pred   = (const float*)d_in[0];
    const float* target = (const float*)d_in[1];
    float* out = (float*)d_out;

    fused_kernel<<<NBLK, 256>>>(pred, target, out);
}

// round 16
// speedup vs baseline: 1.1664x; 1.1664x over previous
#include <cuda_runtime.h>
#include <math.h>

#define IMGS  16
#define H     256
#define W     256
#define NPIX  (H * W)            // 65536
#define TOTAL (IMGS * NPIX)      // 1048576
#define BIG2  1.0e12f            // "no opposite pixel within vertical window"
#define GUARD 9.0f               // exactness guard: excluded cands >= 9
#define NSLAB 32                 // 8-column slabs per image
#define NBLK  (IMGS * NSLAB)     // 512 blocks, fully independent

// ---- accumulators (static __device__; allocation-free per harness rules) ----
__device__ float  d_maxabs[IMGS];
__device__ int    d_counts[IMGS];
__device__ double d_S[IMGS];
__device__ unsigned int d_done;

__device__ __forceinline__ float sqrt_approx(float x) {
    float r;
    asm("sqrt.approx.f32 %0, %1;" : "=f"(r) : "f"(x));
    return r;
}
__device__ __forceinline__ float tanh_approx(float x) {
    float r;
    asm("tanh.approx.f32 %0, %1;" : "=f"(r) : "f"(x));
    return r;
}

// ---------------------------------------------------------------------------
// OUTLINED exact-in-slab fallback (rare: P ~ 2^-26 per pixel). Keeping the
// rolled loops out of the hot function lets ptxas fully unroll the main
// pixel loop and keep all arrays in registers (the R15 defect).
__device__ __noinline__ float edt_fallback(const unsigned* cm, int r, int pj,
                                           float g, float m) {
    for (int j = 0; j < 12; j++) {
        float dx2 = (float)((pj - j) * (pj - j));
        #pragma unroll 1
        for (int y = 0; y < H; y++) {
            unsigned bit = (cm[j * 8 + (y >> 5)] >> (y & 31)) & 1u;
            bool opp = (g > 0.f) ? (bit == 0u) : (bit != 0u);
            if (opp) {
                float dy = (float)(r - y);
                m = fminf(m, fmaf(dy, dy, dx2));
            }
        }
    }
    return m;
}

// ---------------------------------------------------------------------------
// Single fused kernel, Phase-B-free (R15 topology, codegen-fixed).
// Block = one 8-column slab (+2 halo cols -> 12 cols, self-contained for the
// +-2 min-plus window). Thread r: 12-bit row mask -> warp-ballot transpose to
// per-column bitmasks (ONE sync); then per-thread register-only vertical
// +-8-row window distances (funnel shift + clz/ffs), +-2-col min-plus
// (guard 9: excluded candidates have dx^2>=9 or dy^2>=81 -> bm<=9 exact),
// sigmoid, block reduction. Last block finalizes + resets replay state.
__global__ void __launch_bounds__(256, 4)
fused_kernel(const float* __restrict__ pred, const float* __restrict__ target,
             float* __restrict__ out) {
    __shared__ unsigned cmask[12][8];   // per-column 32-row segment bitmasks
    __shared__ float    wred[16];       // 8 warp maxes + 8 warp sums
    __shared__ int      cred[8];        // 8 warp fg-counts
    __shared__ int      is_last;

    int blk  = blockIdx.x;
    int tid  = threadIdx.x;
    int b    = blk >> 5;                // image
    int slab = blk & 31;
    int x0   = slab * 8;
    int r    = tid;                     // this thread's row
    int base = b * NPIX + r * W;
    int warp = tid >> 5, lane = tid & 31;

    // ---- Phase A: masks + pred (front-batched loads) ----
    int wbase = min(max(x0 - 4, 0), W - 16);            // 4-aligned 16-float window
    const float4* tp = (const float4*)(target + base + wbase);
    float4 t0 = tp[0], t1 = tp[1], t2 = tp[2], t3 = tp[3];
    float4 pA = *(const float4*)(pred + base + x0);
    float4 pB = *(const float4*)(pred + base + x0 + 4);

    unsigned mw = 0;
    mw |= (t0.x > 0.5f) ? 1u << 0  : 0u;  mw |= (t0.y > 0.5f) ? 1u << 1  : 0u;
    mw |= (t0.z > 0.5f) ? 1u << 2  : 0u;  mw |= (t0.w > 0.5f) ? 1u << 3  : 0u;
    mw |= (t1.x > 0.5f) ? 1u << 4  : 0u;  mw |= (t1.y > 0.5f) ? 1u << 5  : 0u;
    mw |= (t1.z > 0.5f) ? 1u << 6  : 0u;  mw |= (t1.w > 0.5f) ? 1u << 7  : 0u;
    mw |= (t2.x > 0.5f) ? 1u << 8  : 0u;  mw |= (t2.y > 0.5f) ? 1u << 9  : 0u;
    mw |= (t2.z > 0.5f) ? 1u << 10 : 0u;  mw |= (t2.w > 0.5f) ? 1u << 11 : 0u;
    mw |= (t3.x > 0.5f) ? 1u << 12 : 0u;  mw |= (t3.y > 0.5f) ? 1u << 13 : 0u;
    mw |= (t3.z > 0.5f) ? 1u << 14 : 0u;  mw |= (t3.w > 0.5f) ? 1u << 15 : 0u;

    // rowmask bit j <-> global col clamp(x0-2+j, 0, 255); image-edge halo
    // duplicates the edge column (dominated under max(sg*s+k^2, k^2) -> exact)
    unsigned rm;
    if (slab == 0)            rm = ((mw & 1u) * 3u) | ((mw & 0x3FFu) << 2);
    else if (slab == NSLAB-1) rm = ((mw >> 6) & 0x3FFu) | (((mw >> 15) & 1u) ? (3u << 10) : 0u);
    else                      rm = (mw >> 2) & 0xFFFu;

    int cnt = __popc(rm & 0x3FCu);      // own cols only (j = 2..9)

    #pragma unroll
    for (int j = 0; j < 12; j++) {
        unsigned bal = __ballot_sync(0xffffffffu, (rm >> j) & 1u);
        if (lane == j) cmask[j][warp] = bal;
    }
    __syncthreads();                    // the ONLY pre-reduction barrier

    // ---- vertical window distances, per-thread, in registers ----
    // win bit i <-> row r-8+i (17 bits). validm zeroes out-of-image rows.
    int wlo   = (r - 8) >> 5;           // arithmetic shift: -1 for r < 8
    int shift = (r - 8) & 31;
    unsigned validm = 0x1FFFFu;
    if (r < 8)   validm &= ~((1u << (8 - r)) - 1u);
    if (r > 247) validm &= (1u << (264 - r)) - 1u;

    float v[12];
    #pragma unroll
    for (int j = 0; j < 12; j++) {
        unsigned lo  = (wlo >= 0) ? cmask[j][wlo] : 0u;
        unsigned hi  = (wlo <  7) ? cmask[j][wlo + 1] : 0u;
        unsigned win = __funnelshift_r(lo, hi, shift) & 0x1FFFFu;
        unsigned fgb = (win >> 8) & 1u;
        unsigned opp = (fgb ? ~win : win) & validm;
        unsigned up  = opp & 0xFFu;          // bit i <-> dist 8-i above
        unsigned dn  = opp >> 9;             // bit i <-> dist i+1 below
        int du = up ? (__clz(up) - 23) : 100;
        int dd = dn ? __ffs(dn)        : 100;
        int d  = min(du, dd);
        float v2 = (d > 8) ? BIG2 : (float)(d * d);
        v[j] = fgb ? v2 : -v2;
    }

    // ---- horizontal min-plus window (candidate = max(sg*s[q]+k^2, k^2)) ----
    float bm[8];
    #pragma unroll
    for (int p = 0; p < 8; p++) {            // own col = local j = p+2
        float so = v[p + 2];
        float g  = (so > 0.f) ? 1.f : -1.f;
        float m0 = fmaxf(g * so, 0.f);
        float m1 = fmaxf(fmaf(g, v[p + 1], 1.f), 1.f);
        float m2 = fmaxf(fmaf(g, v[p + 3], 1.f), 1.f);
        float m3 = fmaxf(fmaf(g, v[p],     4.f), 4.f);
        float m4 = fmaxf(fmaf(g, v[p + 4], 4.f), 4.f);
        bm[p] = fminf(fminf(m0, fminf(m1, m2)), fminf(m3, m4));
    }

    // rare deferred fallback (outlined; one guard in the hot path)
    float worst = 0.f;
    #pragma unroll
    for (int p = 0; p < 8; p++) worst = fmaxf(worst, bm[p]);
    if (worst > GUARD) {
        #pragma unroll
        for (int p = 0; p < 8; p++) {
            if (bm[p] > GUARD) {
                float g = (v[p + 2] > 0.f) ? 1.f : -1.f;
                bm[p] = edt_fallback(&cmask[0][0], r, p + 2, g, bm[p]);
            }
        }
    }

    // ---- sigmoid, signed distance, dual accumulator chains ----
    float pv[8] = {pA.x, pA.y, pA.z, pA.w, pB.x, pB.y, pB.z, pB.w};
    float tA = 0.f, tB = 0.f, aA = 0.f, aB = 0.f;
    #pragma unroll
    for (int p = 0; p < 8; p++) {
        float sd   = sqrt_approx(bm[p]);           // bm >= 1 always
        float prob = fmaf(0.5f, tanh_approx(0.5f * pv[p]), 0.5f);
        float sds  = (v[p + 2] > 0.f) ? -sd : sd;  // signed distance
        if (p & 1) { aB = fmaxf(aB, sd); tB = fmaf(prob, sds, tB); }
        else       { aA = fmaxf(aA, sd); tA = fmaf(prob, sds, tA); }
    }
    float term = tA + tB;
    float amax = fmaxf(aA, aB);

    #pragma unroll
    for (int o = 16; o; o >>= 1) {
        amax = fmaxf(amax, __shfl_xor_sync(0xffffffffu, amax, o));
        term +=            __shfl_xor_sync(0xffffffffu, term, o);
        cnt  +=            __shfl_xor_sync(0xffffffffu, cnt,  o);
    }
    if (lane == 0) { wred[warp] = amax; wred[8 + warp] = term; cred[warp] = cnt; }
    __syncthreads();

    if (tid == 0) {
        float  mx = wred[0];
        double sm = (double)wred[8];
        int    cc = cred[0];
        #pragma unroll
        for (int i = 1; i < 8; i++) {
            mx = fmaxf(mx, wred[i]); sm += (double)wred[8 + i]; cc += cred[i];
        }
        atomicMax((int*)&d_maxabs[b], __float_as_int(mx));   // non-neg floats order as ints
        atomicAdd(&d_S[b], sm);
        atomicAdd(&d_counts[b], cc);
        __threadfence();
        unsigned int old = atomicAdd(&d_done, 1u);
        is_last = (old == (unsigned)(NBLK - 1)) ? 1 : 0;
    }
    __syncthreads();

    if (is_last) {
        __threadfence();
        double contrib = 0.0;
        if (tid < IMGS) {
            int    cc = __ldcg(&d_counts[tid]);
            float  mx = __ldcg(&d_maxabs[tid]);
            double S  = __ldcg(&d_S[tid]);
            if (cc > 0 && cc < NPIX)
                contrib = S / ((double)mx + 1e-6);
        }
        if (tid < 32) {
            #pragma unroll
            for (int o = 16; o; o >>= 1)
                contrib += __shfl_xor_sync(0xffffffffu, contrib, o);
            if (tid == 0) *out = (float)(contrib / (double)TOTAL);
        }
        // reset accumulators for the next graph replay
        if (tid < IMGS) { d_S[tid] = 0.0; d_maxabs[tid] = 0.0f; d_counts[tid] = 0; }
        if (tid == 0)   d_done = 0u;
    }
}

// ---------------------------------------------------------------------------
extern "C" void kernel_launch(void* const* d_in, const int* in_sizes, int n_in,
                              void* d_out, int out_size) {
    const float* pred   = (const float*)d_in[0];
    const float* target = (const float*)d_in[1];
    float* out = (float*)d_out;

    fused_kernel<<<NBLK, 256>>>(pred, target, out);
}

// round 17
// speedup vs baseline: 9.8267x; 8.4244x over previous
#include <cuda_runtime.h>
#include <math.h>

#define IMGS  16
#define H     256
#define W     256
#define NPIX  (H * W)            // 65536
#define TOTAL (IMGS * NPIX)      // 1048576
#define BIG2  1.0e12f            // (1e6)^2 for "no opposite pixel in column"
#define BIGF  3.0e37f
#define RWIN  4
#define GUARD 25.0f              // (RWIN+1)^2 exactness guard
#define RPB   4                  // rows per block in the row kernel
#define NROWBLK (IMGS * H / RPB) // 1024

// ---- scratch (static __device__ arrays; allocation-free per harness rules) ----
__device__ float  s_buf[TOTAL];    // signed squared vertical distance: +v^2 (fg) / -v^2 (bg)
__device__ float  d_maxabs[IMGS];
__device__ int    d_counts[IMGS];
__device__ double d_S[IMGS];
__device__ unsigned int d_done;    // completion counter for fused finalize

__device__ __forceinline__ float sqrt_approx(float x) {
    float r;
    asm("sqrt.approx.f32 %0, %1;" : "=f"(r) : "f"(x));
    return r;
}

// ---------------------------------------------------------------------------
// Vertical EDT pass (record-holder version). 128 blocks x 256 threads: each
// thread owns a 32-row segment of one column; bitmask loads (full MLP),
// clz/ffs segment summaries combined in shared, 32-step unrolled SEL chains.
// Ends with griddepcontrol.launch_dependents (PDL).
__global__ void col_pass_kernel(const float* __restrict__ target) {
    __shared__ int sHiF[8][32], sHiB[8][32];
    __shared__ int sLoF[8][32], sLoB[8][32];

    int blk   = blockIdx.x;
    int tid   = threadIdx.x;
    int b     = blk >> 3;
    int chunk = blk & 7;
    int t     = tid & 31;      // local column
    int w     = tid >> 5;      // 32-row segment
    int x     = chunk * 32 + t;
    int ybase = w * 32;

    const float* m = target + b * NPIX + x;
    unsigned word = 0;
    #pragma unroll
    for (int j = 0; j < 32; j++)
        if (m[(ybase + j) * W] > 0.5f) word |= (1u << j);
    int cnt = __popc(word);

    unsigned nw = ~word;
    sHiF[w][t] = word ? (ybase + 31 - __clz(word)) : -1000000;
    sHiB[w][t] = nw   ? (ybase + 31 - __clz(nw))   : -1000000;
    sLoF[w][t] = word ? (ybase + __ffs(word) - 1)  :  1000000;
    sLoB[w][t] = nw   ? (ybase + __ffs(nw) - 1)    :  1000000;
    __syncthreads();

    int lastf = -1000000, lastb = -1000000;
    for (int w2 = 0; w2 < w; w2++) {
        lastf = max(lastf, sHiF[w2][t]);
        lastb = max(lastb, sHiB[w2][t]);
    }
    int nextf = 1000000, nextb = 1000000;
    for (int w2 = w + 1; w2 < 8; w2++) {
        nextf = min(nextf, sLoF[w2][t]);
        nextb = min(nextb, sLoB[w2][t]);
    }

    // forward chain: distance to nearest opposite-class pixel above (u16 packed)
    unsigned pk[16];
    #pragma unroll
    for (int j = 0; j < 32; j++) {
        int  y  = ybase + j;
        bool fg = (word >> j) & 1;
        int  da = y - (fg ? lastb : lastf);
        if (da > 1000) da = 1000;
        if (j & 1) pk[j >> 1] |= ((unsigned)da << 16);
        else       pk[j >> 1]  =  (unsigned)da;
        if (fg) lastf = y; else lastb = y;
    }
    // backward chain + combine + store signed v^2
    float* sbp = s_buf + b * NPIX + x;
    #pragma unroll
    for (int j = 31; j >= 0; j--) {
        int  y  = ybase + j;
        bool fg = (word >> j) & 1;
        int  db = (fg ? nextb : nextf) - y;
        if (fg) nextf = y; else nextb = y;
        int da = (int)((pk[j >> 1] >> ((j & 1) * 16)) & 0xffffu);
        int d  = min(da, db);
        float v2 = (d > 255) ? BIG2 : (float)(d * d);
        sbp[y * W] = fg ? v2 : -v2;
    }

    #pragma unroll
    for (int o = 16; o; o >>= 1) cnt += __shfl_xor_sync(0xffffffffu, cnt, o);
    if (t == 0) atomicAdd(&d_counts[b], cnt);

    // PDL: all s_buf stores above are visible to dependent-kernel reads
    asm volatile("griddepcontrol.launch_dependents;" ::: "memory");
}

// ---------------------------------------------------------------------------
// Fused row min-plus + sigmoid + per-image reduction + last-block finalize.
// RECORD-HOLDER geometry & math (14.5 us run): 1024 blocks x 256 threads,
// 4 rows/block, 4 px/thread, RWIN=4 / GUARD=25, signed shared array with
// candidate = max(sg*s[q] + k^2, k^2), __expf sigmoid, sqrt.approx.
// Only delta: PDL — pred load + sigmoid hoisted before griddepcontrol.wait.
__global__ void row_fused_kernel(const float* __restrict__ pred, float* __restrict__ out) {
    int blk  = blockIdx.x;
    int b    = blk >> 6;                 // 64 blocks per image
    int y0   = (blk & 63) * RPB;
    int tid  = threadIdx.x;
    int r    = tid >> 6;                 // row within block: 0..3
    int c    = tid & 63;                 // pixel-quad within row
    int base = b * NPIX + (y0 + r) * W;
    int x0   = c * 4;

    __shared__ float sh[RPB][W + 8];     // signed s tiles, +4 halo each side
    __shared__ float wred[16];           // 8 warp maxes + 8 warp sums
    __shared__ int   is_last;

    // ---- pre-dependency work: pred is a harness input, valid immediately ----
    float4 p4 = *(const float4*)(pred + base + x0);
    float prob[4];
    prob[0] = __fdividef(1.f, 1.f + __expf(-p4.x));
    prob[1] = __fdividef(1.f, 1.f + __expf(-p4.y));
    prob[2] = __fdividef(1.f, 1.f + __expf(-p4.z));
    prob[3] = __fdividef(1.f, 1.f + __expf(-p4.w));

    // ---- wait for col kernel's s_buf stores (no-op without PDL attr) ----
    asm volatile("griddepcontrol.wait;" ::: "memory");

    float4 s4 = *(const float4*)(s_buf + base + x0);
    *(float4*)&sh[r][x0 + 4] = s4;
    if (c == 0)  { sh[r][0] = s4.x; sh[r][1] = s4.x; sh[r][2] = s4.x; sh[r][3] = s4.x; }
    if (c == 63) { sh[r][W+4] = s4.w; sh[r][W+5] = s4.w; sh[r][W+6] = s4.w; sh[r][W+7] = s4.w; }
    __syncthreads();

    // v[i] = sh[r][x0 + i], i=0..11 covers logical offsets -4..+7
    float v[12];
    #pragma unroll
    for (int i = 0; i < 3; i++) {
        float4 a = *(const float4*)&sh[r][x0 + 4 * i];
        v[4*i] = a.x; v[4*i+1] = a.y; v[4*i+2] = a.z; v[4*i+3] = a.w;
    }

    float term = 0.f, amax = 0.f;
    #pragma unroll
    for (int p = 0; p < 4; p++) {
        float s_own = v[p + 4];
        float sg    = (s_own > 0.f) ? 1.f : -1.f;       // +1 fg, -1 bg
        float bmin  = BIGF;
        #pragma unroll
        for (int j = 0; j < 9; j++) {                   // q = x + (j-4)
            float kk = (float)((j - 4) * (j - 4));
            bmin = fminf(bmin, fmaxf(fmaf(sg, v[p + j], kk), kk));
        }
        if (bmin > GUARD) {                             // rare exact full-row fallback
            float xp = (float)(x0 + p);
            bmin = BIGF;
            #pragma unroll 1
            for (int q = 0; q < W; q++) {
                float dx = xp - (float)q;
                float kk = dx * dx;
                bmin = fminf(bmin, fmaxf(fmaf(sg, sh[r][q + 4], kk), kk));
            }
        }
        float sd  = sqrt_approx(bmin);                  // bmin >= 1 always
        amax      = fmaxf(amax, sd);
        float sds = (s_own > 0.f) ? -sd : sd;           // signed distance
        term      = fmaf(prob[p], sds, term);
    }

    #pragma unroll
    for (int o = 16; o; o >>= 1) {
        amax = fmaxf(amax, __shfl_xor_sync(0xffffffffu, amax, o));
        term +=            __shfl_xor_sync(0xffffffffu, term, o);
    }
    int lane = tid & 31, wp = tid >> 5;
    if (lane == 0) { wred[wp] = amax; wred[8 + wp] = term; }
    __syncthreads();

    if (tid == 0) {
        float  mx = wred[0];
        double sm = (double)wred[8];
        #pragma unroll
        for (int i = 1; i < 8; i++) { mx = fmaxf(mx, wred[i]); sm += (double)wred[8 + i]; }
        atomicMax((int*)&d_maxabs[b], __float_as_int(mx));   // non-neg floats order as ints
        atomicAdd(&d_S[b], sm);
        __threadfence();
        unsigned int old = atomicAdd(&d_done, 1u);
        is_last = (old == (unsigned)(NROWBLK - 1)) ? 1 : 0;
    }
    __syncthreads();

    if (is_last) {
        __threadfence();
        double contrib = 0.0;
        if (tid < IMGS) {
            int    cc = __ldcg(&d_counts[tid]);
            float  mx = __ldcg(&d_maxabs[tid]);
            double S  = __ldcg(&d_S[tid]);
            if (cc > 0 && cc < NPIX)
                contrib = S / ((double)mx + 1e-6);
        }
        if (tid < 32) {
            #pragma unroll
            for (int o = 16; o; o >>= 1)
                contrib += __shfl_xor_sync(0xffffffffu, contrib, o);
            if (tid == 0) *out = (float)(contrib / (double)TOTAL);
        }
        // reset accumulators for the next graph replay
        if (tid < IMGS) { d_S[tid] = 0.0; d_maxabs[tid] = 0.0f; d_counts[tid] = 0; }
        if (tid == 0)   d_done = 0u;
    }
}

// ---------------------------------------------------------------------------
extern "C" void kernel_launch(void* const* d_in, const int* in_sizes, int n_in,
                              void* d_out, int out_size) {
    const float* pred   = (const float*)d_in[0];
    const float* target = (const float*)d_in[1];
    float* out = (float*)d_out;

    col_pass_kernel<<<IMGS * 8, 256>>>(target);

    // Programmatic dependent launch: row kernel dispatches while col runs;
    // its griddepcontrol.wait gates the s_buf reads.
    cudaLaunchConfig_t cfg = {};
    cfg.gridDim  = dim3(NROWBLK);
    cfg.blockDim = dim3(256);
    cfg.dynamicSmemBytes = 0;
    cfg.stream = 0;
    cudaLaunchAttribute attrs[1];
    attrs[0].id = cudaLaunchAttributeProgrammaticStreamSerialization;
    attrs[0].val.programmaticStreamSerializationAllowed = 1;
    cfg.attrs = attrs;
    cfg.numAttrs = 1;
    cudaError_t e = cudaLaunchKernelEx(&cfg, row_fused_kernel, pred, out);
    if (e != cudaSuccess) {
        // fallback: plain serialized launch (griddepcontrol.wait is a no-op)
        row_fused_kernel<<<NROWBLK, 256>>>(pred, out);
    }
}